// round 3
// baseline (speedup 1.0000x reference)
#include <cuda_runtime.h>
#include <cuda_bf16.h>

#define WARPS_PER_BLOCK 8
#define THREADS_PER_BLOCK (WARPS_PER_BLOCK * 32)
#define MAX_NODES (1 << 17)   // >= 100000; scratch for per-node inverse norms

__device__ float g_inv_norm[MAX_NODES];

// ---------------------------------------------------------------------------
// Prologue: inv_norm[n] = 1/||features[n,:]||  (one warp per node, D=128)
// ---------------------------------------------------------------------------
__global__ __launch_bounds__(THREADS_PER_BLOCK)
void node_norms_kernel(const float* __restrict__ features, int N)
{
    const unsigned FULL = 0xffffffffu;
    const int lane = threadIdx.x & 31;
    const int node = blockIdx.x * WARPS_PER_BLOCK + (threadIdx.x >> 5);
    if (node >= N) return;

    const float4 v = reinterpret_cast<const float4*>(features)[(size_t)node * 32 + lane];
    float s = v.x * v.x;
    s = fmaf(v.y, v.y, s);
    s = fmaf(v.z, v.z, s);
    s = fmaf(v.w, v.w, s);
    #pragma unroll
    for (int w = 16; w >= 1; w >>= 1)
        s += __shfl_xor_sync(FULL, s, w);

    if (lane == 0) {
        float r = rsqrtf(s);
        r = r * fmaf(-0.5f * s, r * r, 1.5f);   // one Newton step -> ~fp32-exact
        g_inv_norm[node] = r;
    }
}

// merge two per-lane partial sums across the xor-w fold of the warp
__device__ __forceinline__ float merge_f(float a, float b, int w, int lane) {
    const unsigned FULL = 0xffffffffu;
    const float keep = (lane & w) ? b : a;
    const float send = (lane & w) ? a : b;
    return keep + __shfl_xor_sync(FULL, send, w);
}

// ---------------------------------------------------------------------------
// Main: one warp per batch row. D=128 (32 float4, one per lane). K=32.
// ---------------------------------------------------------------------------
__global__ __launch_bounds__(THREADS_PER_BLOCK)
void intra_agg_kernel(const float* __restrict__ features,
                      const int*   __restrict__ nodes,
                      const int*   __restrict__ neighs,
                      const int*   __restrict__ nsamp,
                      float*       __restrict__ out,
                      int B, int K)
{
    const unsigned FULL = 0xffffffffu;
    const int lane = threadIdx.x & 31;
    const int row  = blockIdx.x * WARPS_PER_BLOCK + (threadIdx.x >> 5);
    if (row >= B) return;

    const int ns = nsamp ? nsamp[0] : 10;

    const float4* __restrict__ F = reinterpret_cast<const float4*>(features);
    const int* __restrict__ nrow = neighs + (size_t)row * K;

    // per-lane candidate index (lane k owns candidate k)
    const int kc = (lane < K) ? lane : (K - 1);
    const int my_neigh = nrow[kc];

    // center row: one coalesced 512B load
    const float4 c = F[(size_t)nodes[row] * 32 + lane];

    float my_dot = 0.0f;

    // ---- Phase 1: 4 groups x 8 cooperative dots (MLP=8 row gathers) ----
    #pragma unroll
    for (int g = 0; g < 4; g++) {
        int idx[8];
        #pragma unroll
        for (int u = 0; u < 8; u++)                 // warp-uniform: L1 broadcast
            idx[u] = __ldg(&nrow[g * 8 + u]);

        float4 f[8];
        #pragma unroll
        for (int u = 0; u < 8; u++)                 // 8 independent 512B gathers
            f[u] = F[(size_t)idx[u] * 32 + lane];

        float dp[8];
        #pragma unroll
        for (int u = 0; u < 8; u++) {
            float d = c.x * f[u].x;
            d = fmaf(c.y, f[u].y, d);
            d = fmaf(c.z, f[u].z, d);
            dp[u] = fmaf(c.w, f[u].w, d);
        }

        // transpose-reduce 8 values across 32 lanes: 9 shfls total
        float b0 = merge_f(dp[0], dp[4], 16, lane);
        float b1 = merge_f(dp[1], dp[5], 16, lane);
        float b2 = merge_f(dp[2], dp[6], 16, lane);
        float b3 = merge_f(dp[3], dp[7], 16, lane);
        float c0 = merge_f(b0, b2, 8, lane);
        float c1 = merge_f(b1, b3, 8, lane);
        float d  = merge_f(c0, c1, 4, lane);
        d += __shfl_xor_sync(FULL, d, 2);
        d += __shfl_xor_sync(FULL, d, 1);
        // lane L now holds full dot of value j = bit2(L) + 2*bit3(L) + 4*bit4(L)

        const float t = __shfl_sync(FULL, d, (lane & 7) << 2);  // j = lane&7
        if ((lane >> 3) == g) my_dot = t;
    }

    // key = dot / ||neigh||  (center norm = common positive factor, dropped)
    float my_key = my_dot * g_inv_norm[my_neigh];
    if (lane >= K) my_key = -1e30f;   // defensive for K<32 (K==32 here)

    // ---- stable rank-by-counting (matches jax.lax.top_k tie-break) ----
    int rank = 0;
    for (int j = 0; j < K; j++) {
        const float kj = __shfl_sync(FULL, my_key, j);
        rank += (kj > my_key) || (kj == my_key && j < lane);
    }

    // ---- Phase 2: mean over selected neighbors (reload: L1-warm) ----
    unsigned sel = __ballot_sync(FULL, (rank < ns) && (lane < K));
    float4 acc = make_float4(0.f, 0.f, 0.f, 0.f);
    while (sel) {
        const int j = __ffs(sel) - 1;
        sel &= sel - 1;
        const int nidx = __shfl_sync(FULL, my_neigh, j);
        const float4 v = F[(size_t)nidx * 32 + lane];
        acc.x += v.x; acc.y += v.y; acc.z += v.z; acc.w += v.w;
    }

    const float inv = 1.0f / (float)ns;
    float4 o;
    o.x = fmaxf(acc.x * inv, 0.0f);
    o.y = fmaxf(acc.y * inv, 0.0f);
    o.z = fmaxf(acc.z * inv, 0.0f);
    o.w = fmaxf(acc.w * inv, 0.0f);
    reinterpret_cast<float4*>(out)[(size_t)row * 32 + lane] = o;
}

extern "C" void kernel_launch(void* const* d_in, const int* in_sizes, int n_in,
                              void* d_out, int out_size)
{
    const float* features = (const float*)d_in[0];
    const int*   nodes    = (const int*)d_in[1];
    const int*   neighs   = (const int*)d_in[2];
    const int*   nsamp    = (n_in >= 4) ? (const int*)d_in[3] : nullptr;
    float*       out      = (float*)d_out;

    const int N = in_sizes[0] / 128;
    const int B = in_sizes[1];
    const int K = in_sizes[2] / B;   // 32

    const int nblocks = (N + WARPS_PER_BLOCK - 1) / WARPS_PER_BLOCK;
    node_norms_kernel<<<nblocks, THREADS_PER_BLOCK>>>(features, N);

    const int blocks = (B + WARPS_PER_BLOCK - 1) / WARPS_PER_BLOCK;
    intra_agg_kernel<<<blocks, THREADS_PER_BLOCK>>>(features, nodes, neighs, nsamp,
                                                    out, B, K);
}

// round 4
// speedup vs baseline: 1.1393x; 1.1393x over previous
#include <cuda_runtime.h>
#include <cuda_bf16.h>

#define WARPS_PER_BLOCK 8
#define THREADS_PER_BLOCK (WARPS_PER_BLOCK * 32)

static __device__ __forceinline__ float merge_f(float a, float b, int w, int lane) {
    const unsigned FULL = 0xffffffffu;
    const float keep = (lane & w) ? b : a;
    const float send = (lane & w) ? a : b;
    return keep + __shfl_xor_sync(FULL, send, w);
}

// Transpose-reduce 8 per-lane partial sums across the warp.
// Returns, in lane L, the fully-reduced value j = L & 7.  (10 shfls)
static __device__ __forceinline__ float xpose_reduce8(const float* dp, int lane) {
    const unsigned FULL = 0xffffffffu;
    float b0 = merge_f(dp[0], dp[4], 16, lane);
    float b1 = merge_f(dp[1], dp[5], 16, lane);
    float b2 = merge_f(dp[2], dp[6], 16, lane);
    float b3 = merge_f(dp[3], dp[7], 16, lane);
    float c0 = merge_f(b0, b2, 8, lane);
    float c1 = merge_f(b1, b3, 8, lane);
    float d  = merge_f(c0, c1, 4, lane);
    d += __shfl_xor_sync(FULL, d, 2);
    d += __shfl_xor_sync(FULL, d, 1);
    // lane L holds value j = bit2(L) + 2*bit3(L) + 4*bit4(L); redistribute:
    return __shfl_sync(FULL, d, (lane & 7) << 2);
}

// One warp per batch row. D=128 floats (32 float4, one per lane). K=32.
__global__ __launch_bounds__(THREADS_PER_BLOCK)
void intra_agg_kernel(const float* __restrict__ features,
                      const int*   __restrict__ nodes,
                      const int*   __restrict__ neighs,
                      const int*   __restrict__ nsamp,
                      float*       __restrict__ out,
                      int B, int K)
{
    const unsigned FULL = 0xffffffffu;
    const int lane = threadIdx.x & 31;
    const int row  = blockIdx.x * WARPS_PER_BLOCK + (threadIdx.x >> 5);
    if (row >= B) return;

    const int ns = nsamp ? nsamp[0] : 10;

    const float4* __restrict__ F = reinterpret_cast<const float4*>(features);
    const int* __restrict__ nrow = neighs + (size_t)row * K;

    // per-lane candidate index (lane k owns candidate k)
    const int kc = (lane < K) ? lane : (K - 1);
    const int my_neigh = nrow[kc];

    // center row: one coalesced 512B load
    const float4 c = F[(size_t)nodes[row] * 32 + lane];

    float my_dot = 0.0f;
    float my_n2  = 1.0f;

    // ---- Phase 1: 4 groups x 8 cooperative dot+norm (MLP=8 row gathers) ----
    #pragma unroll
    for (int g = 0; g < 4; g++) {
        int idx[8];
        #pragma unroll
        for (int u = 0; u < 8; u++)                 // warp-uniform: L1 broadcast
            idx[u] = __ldg(&nrow[g * 8 + u]);

        float4 f[8];
        #pragma unroll
        for (int u = 0; u < 8; u++)                 // 8 independent 512B gathers
            f[u] = F[(size_t)idx[u] * 32 + lane];

        float dp[8], np[8];
        #pragma unroll
        for (int u = 0; u < 8; u++) {
            float d = c.x * f[u].x;
            d = fmaf(c.y, f[u].y, d);
            d = fmaf(c.z, f[u].z, d);
            dp[u] = fmaf(c.w, f[u].w, d);
            float n = f[u].x * f[u].x;
            n = fmaf(f[u].y, f[u].y, n);
            n = fmaf(f[u].z, f[u].z, n);
            np[u] = fmaf(f[u].w, f[u].w, n);
        }

        const float dot_j = xpose_reduce8(dp, lane);   // lane L: dot of cand (g*8 + (L&7))
        const float n2_j  = xpose_reduce8(np, lane);
        if ((lane >> 3) == g) { my_dot = dot_j; my_n2 = n2_j; }
    }

    // key = dot / ||neigh||  (center norm = common positive factor, dropped)
    float r = rsqrtf(my_n2);
    r = r * fmaf(-0.5f * my_n2, r * r, 1.5f);          // Newton -> ~fp32-exact
    float my_key = my_dot * r;
    if (lane >= K) my_key = -1e30f;

    // ---- stable rank-by-counting (matches jax.lax.top_k tie-break) ----
    int rank = 0;
    for (int j = 0; j < K; j++) {
        const float kj = __shfl_sync(FULL, my_key, j);
        rank += (kj > my_key) || (kj == my_key && j < lane);
    }

    // ---- Phase 2: mean over selected neighbors ----
    unsigned sel = __ballot_sync(FULL, (rank < ns) && (lane < K));
    float4 acc = make_float4(0.f, 0.f, 0.f, 0.f);

    if (ns == 10) {
        // compile-time trip count: addresses first, then batched MLP-5 loads
        int src[10];
        unsigned m = sel;
        #pragma unroll
        for (int s = 0; s < 10; s++) { src[s] = __ffs(m) - 1; m &= m - 1; }
        int nid[10];
        #pragma unroll
        for (int s = 0; s < 10; s++) nid[s] = __shfl_sync(FULL, my_neigh, src[s]);
        #pragma unroll
        for (int s0 = 0; s0 < 10; s0 += 5) {
            float4 v[5];
            #pragma unroll
            for (int u = 0; u < 5; u++)
                v[u] = F[(size_t)nid[s0 + u] * 32 + lane];
            #pragma unroll
            for (int u = 0; u < 5; u++) {
                acc.x += v[u].x; acc.y += v[u].y;
                acc.z += v[u].z; acc.w += v[u].w;
            }
        }
    } else {
        while (sel) {
            const int j = __ffs(sel) - 1;
            sel &= sel - 1;
            const int nidx = __shfl_sync(FULL, my_neigh, j);
            const float4 v = F[(size_t)nidx * 32 + lane];
            acc.x += v.x; acc.y += v.y; acc.z += v.z; acc.w += v.w;
        }
    }

    const float inv = 1.0f / (float)ns;
    float4 o;
    o.x = fmaxf(acc.x * inv, 0.0f);
    o.y = fmaxf(acc.y * inv, 0.0f);
    o.z = fmaxf(acc.z * inv, 0.0f);
    o.w = fmaxf(acc.w * inv, 0.0f);
    __stcs(reinterpret_cast<float4*>(out) + (size_t)row * 32 + lane, o);  // streaming: don't evict table
}

extern "C" void kernel_launch(void* const* d_in, const int* in_sizes, int n_in,
                              void* d_out, int out_size)
{
    const float* features = (const float*)d_in[0];
    const int*   nodes    = (const int*)d_in[1];
    const int*   neighs   = (const int*)d_in[2];
    const int*   nsamp    = (n_in >= 4) ? (const int*)d_in[3] : nullptr;
    float*       out      = (float*)d_out;

    const int B = in_sizes[1];
    const int K = in_sizes[2] / B;   // 32

    const int blocks = (B + WARPS_PER_BLOCK - 1) / WARPS_PER_BLOCK;
    intra_agg_kernel<<<blocks, THREADS_PER_BLOCK>>>(features, nodes, neighs, nsamp,
                                                    out, B, K);
}

// round 5
// speedup vs baseline: 1.2321x; 1.0814x over previous
#include <cuda_runtime.h>
#include <cuda_bf16.h>

#define WARPS_PER_BLOCK 8
#define THREADS_PER_BLOCK (WARPS_PER_BLOCK * 32)

// One warp per batch row. D=128 floats (row = 32 float4). K=32 (hardwired).
// Phase 1 layout: 4 octets (8 lanes each); slot s: octet o handles candidate
// c = 4s + o, loading its 512B row as 4 x 128B chunks (1 line per octet per LDG).
__global__ __launch_bounds__(THREADS_PER_BLOCK)
void intra_agg_kernel(const float* __restrict__ features,
                      const int*   __restrict__ nodes,
                      const int*   __restrict__ neighs,
                      const int*   __restrict__ nsamp,
                      float*       __restrict__ out,
                      int B)
{
    const unsigned FULL = 0xffffffffu;
    const int lane = threadIdx.x & 31;
    const int row  = blockIdx.x * WARPS_PER_BLOCK + (threadIdx.x >> 5);
    if (row >= B) return;

    const int ns = nsamp ? nsamp[0] : 10;

    const float4* __restrict__ F = reinterpret_cast<const float4*>(features);
    const int* __restrict__ nrow = neighs + (size_t)row * 32;

    const int my_neigh = nrow[lane];              // lane k owns candidate k
    const int oct      = lane >> 3;               // my octet (0..3)
    const int ol       = lane & 7;                // lane within octet

    // center row: lane holds floats [4*lane, 4*lane+4)
    const float4 c_my = F[(size_t)nodes[row] * 32 + lane];
    // center chunk view for octet layout: chunk t, lane ol -> float4 index t*8+ol
    // (fetch via shfl from the lane that owns it: src = t*8 + ol)
    float4 cc[4];
    #pragma unroll
    for (int t = 0; t < 4; t++) {
        const int src = t * 8 + ol;
        cc[t].x = __shfl_sync(FULL, c_my.x, src);
        cc[t].y = __shfl_sync(FULL, c_my.y, src);
        cc[t].z = __shfl_sync(FULL, c_my.z, src);
        cc[t].w = __shfl_sync(FULL, c_my.w, src);
    }

    float my_dot = 0.0f;
    float my_n2  = 1.0f;

    // ---- Phase 1: 8 slots x 4 octet-parallel candidates ----
    #pragma unroll
    for (int s = 0; s < 8; s++) {
        const int cidx = __shfl_sync(FULL, my_neigh, s * 4 + oct);  // my octet's candidate

        float4 f[4];
        const float4* base = F + (size_t)cidx * 32 + ol;
        #pragma unroll
        for (int t = 0; t < 4; t++)          // 4 x 128B chunks (4 lines per LDG instr)
            f[t] = base[t * 8];

        float dp = 0.0f, np = 0.0f;
        #pragma unroll
        for (int t = 0; t < 4; t++) {
            dp = fmaf(cc[t].x, f[t].x, dp);
            dp = fmaf(cc[t].y, f[t].y, dp);
            dp = fmaf(cc[t].z, f[t].z, dp);
            dp = fmaf(cc[t].w, f[t].w, dp);
            np = fmaf(f[t].x, f[t].x, np);
            np = fmaf(f[t].y, f[t].y, np);
            np = fmaf(f[t].z, f[t].z, np);
            np = fmaf(f[t].w, f[t].w, np);
        }

        // octet-local butterfly (stays within octet for w<8)
        #pragma unroll
        for (int w = 4; w >= 1; w >>= 1) {
            dp += __shfl_xor_sync(FULL, dp, w);
            np += __shfl_xor_sync(FULL, np, w);
        }

        // deliver candidate L's results to lane L (c = 4s+o -> o=L&3, s=L>>2)
        const int src = (lane & 3) << 3;
        const float db = __shfl_sync(FULL, dp, src);
        const float nb = __shfl_sync(FULL, np, src);
        if ((lane >> 2) == s) { my_dot = db; my_n2 = nb; }
    }

    // key = dot / ||neigh||  (center norm: common positive factor, dropped)
    float r = rsqrtf(my_n2);
    r = r * fmaf(-0.5f * my_n2, r * r, 1.5f);       // Newton -> ~fp32-exact
    const float my_key = my_dot * r;

    // ---- stable rank-by-counting (matches jax.lax.top_k tie-break) ----
    int rank = 0;
    #pragma unroll 8
    for (int j = 0; j < 32; j++) {
        const float kj = __shfl_sync(FULL, my_key, j);
        rank += (kj > my_key) || (kj == my_key && j < lane);
    }

    // ---- Phase 2: mean over selected neighbors ----
    const unsigned sel = __ballot_sync(FULL, rank < ns);
    float4 acc = make_float4(0.f, 0.f, 0.f, 0.f);

    if (ns == 10) {
        int src10[10];
        unsigned m = sel;
        #pragma unroll
        for (int s = 0; s < 10; s++) { src10[s] = __ffs(m) - 1; m &= m - 1; }
        int nid[10];
        #pragma unroll
        for (int s = 0; s < 10; s++) nid[s] = __shfl_sync(FULL, my_neigh, src10[s]);
        #pragma unroll
        for (int s0 = 0; s0 < 10; s0 += 5) {
            float4 v[5];
            #pragma unroll
            for (int u = 0; u < 5; u++)
                v[u] = F[(size_t)nid[s0 + u] * 32 + lane];
            #pragma unroll
            for (int u = 0; u < 5; u++) {
                acc.x += v[u].x; acc.y += v[u].y;
                acc.z += v[u].z; acc.w += v[u].w;
            }
        }
    } else {
        unsigned m = sel;
        while (m) {
            const int j = __ffs(m) - 1;
            m &= m - 1;
            const int nidx = __shfl_sync(FULL, my_neigh, j);
            const float4 v = F[(size_t)nidx * 32 + lane];
            acc.x += v.x; acc.y += v.y; acc.z += v.z; acc.w += v.w;
        }
    }

    const float inv = 1.0f / (float)ns;
    float4 o;
    o.x = fmaxf(acc.x * inv, 0.0f);
    o.y = fmaxf(acc.y * inv, 0.0f);
    o.z = fmaxf(acc.z * inv, 0.0f);
    o.w = fmaxf(acc.w * inv, 0.0f);
    __stcs(reinterpret_cast<float4*>(out) + (size_t)row * 32 + lane, o);
}

extern "C" void kernel_launch(void* const* d_in, const int* in_sizes, int n_in,
                              void* d_out, int out_size)
{
    const float* features = (const float*)d_in[0];
    const int*   nodes    = (const int*)d_in[1];
    const int*   neighs   = (const int*)d_in[2];
    const int*   nsamp    = (n_in >= 4) ? (const int*)d_in[3] : nullptr;
    float*       out      = (float*)d_out;

    const int B = in_sizes[1];

    const int blocks = (B + WARPS_PER_BLOCK - 1) / WARPS_PER_BLOCK;
    intra_agg_kernel<<<blocks, THREADS_PER_BLOCK>>>(features, nodes, neighs, nsamp,
                                                    out, B);
}

// round 6
// speedup vs baseline: 1.2505x; 1.0150x over previous
#include <cuda_runtime.h>
#include <cuda_bf16.h>

#define WARPS_PER_BLOCK 8
#define THREADS_PER_BLOCK (WARPS_PER_BLOCK * 32)

// One warp per batch row. D=128 floats (row = 32 float4). K=32 (hardwired).
// Octet layout: 4 octets (8 lanes); slot s: octet o handles candidate c = 4s+o,
// loading its 512B row as 4 x 128B chunks. Software-pipelined one slot ahead.
__global__ __launch_bounds__(THREADS_PER_BLOCK, 4)
void intra_agg_kernel(const float* __restrict__ features,
                      const int*   __restrict__ nodes,
                      const int*   __restrict__ neighs,
                      const int*   __restrict__ nsamp,
                      float*       __restrict__ out,
                      int B)
{
    const unsigned FULL = 0xffffffffu;
    const int lane = threadIdx.x & 31;
    const int row  = blockIdx.x * WARPS_PER_BLOCK + (threadIdx.x >> 5);
    if (row >= B) return;

    const int ns = nsamp ? nsamp[0] : 10;

    const float4* __restrict__ F = reinterpret_cast<const float4*>(features);
    const int* __restrict__ nrow = neighs + (size_t)row * 32;

    const int my_neigh = nrow[lane];              // lane k owns candidate k
    const int oct      = lane >> 3;               // my octet (0..3)
    const int ol       = lane & 7;                // lane within octet

    // center row directly in octet-chunk layout: cc[t] = floats [4*(t*8+ol) ..)
    const float4* cbase = F + (size_t)nodes[row] * 32 + ol;
    float4 cc[4];
    #pragma unroll
    for (int t = 0; t < 4; t++) cc[t] = cbase[t * 8];

    float my_dot = 0.0f;
    float my_n2  = 1.0f;

    // ---- Phase 1: 8 slots x 4 octet-parallel candidates, pipelined depth-1 ----
    int cidx = __shfl_sync(FULL, my_neigh, oct);  // slot 0 candidate for my octet
    const float4* base = F + (size_t)cidx * 32 + ol;
    float4 f[4];
    #pragma unroll
    for (int t = 0; t < 4; t++) f[t] = base[t * 8];

    #pragma unroll
    for (int s = 0; s < 8; s++) {
        // prefetch slot s+1 (loads in flight across this slot's compute)
        float4 g[4];
        if (s < 7) {
            const int nxt = __shfl_sync(FULL, my_neigh, (s + 1) * 4 + oct);
            const float4* nb = F + (size_t)nxt * 32 + ol;
            #pragma unroll
            for (int t = 0; t < 4; t++) g[t] = nb[t * 8];
        }

        float dp = 0.0f, np = 0.0f;
        #pragma unroll
        for (int t = 0; t < 4; t++) {
            dp = fmaf(cc[t].x, f[t].x, dp);
            dp = fmaf(cc[t].y, f[t].y, dp);
            dp = fmaf(cc[t].z, f[t].z, dp);
            dp = fmaf(cc[t].w, f[t].w, dp);
            np = fmaf(f[t].x, f[t].x, np);
            np = fmaf(f[t].y, f[t].y, np);
            np = fmaf(f[t].z, f[t].z, np);
            np = fmaf(f[t].w, f[t].w, np);
        }

        // octet-local butterfly (w<8 stays within octet)
        #pragma unroll
        for (int w = 4; w >= 1; w >>= 1) {
            dp += __shfl_xor_sync(FULL, dp, w);
            np += __shfl_xor_sync(FULL, np, w);
        }

        // deliver candidate L's results to lane L (c = 4s+o -> o=L&3, s=L>>2)
        const int src = (lane & 3) << 3;
        const float db = __shfl_sync(FULL, dp, src);
        const float nb2 = __shfl_sync(FULL, np, src);
        if ((lane >> 2) == s) { my_dot = db; my_n2 = nb2; }

        if (s < 7) {
            #pragma unroll
            for (int t = 0; t < 4; t++) f[t] = g[t];
        }
    }

    // key = dot / ||neigh||  (center norm: common positive factor, dropped)
    float r = rsqrtf(my_n2);
    r = r * fmaf(-0.5f * my_n2, r * r, 1.5f);     // Newton -> ~fp32-exact
    const float my_key = my_dot * r;

    // ---- stable rank-by-counting (matches jax.lax.top_k tie-break) ----
    int rank = 0;
    #pragma unroll
    for (int j = 0; j < 32; j++) {
        const float kj = __shfl_sync(FULL, my_key, j);
        rank += (kj > my_key) || (kj == my_key && j < lane);
    }

    // ---- Phase 2: mean over selected neighbors ----
    const unsigned sel = __ballot_sync(FULL, rank < ns);
    float4 acc = make_float4(0.f, 0.f, 0.f, 0.f);

    if (ns == 10) {
        int src10[10];
        unsigned m = sel;
        #pragma unroll
        for (int s = 0; s < 10; s++) { src10[s] = __ffs(m) - 1; m &= m - 1; }
        int nid[10];
        #pragma unroll
        for (int s = 0; s < 10; s++) nid[s] = __shfl_sync(FULL, my_neigh, src10[s]);
        #pragma unroll
        for (int s0 = 0; s0 < 10; s0 += 5) {
            float4 v[5];
            #pragma unroll
            for (int u = 0; u < 5; u++)
                v[u] = F[(size_t)nid[s0 + u] * 32 + lane];
            #pragma unroll
            for (int u = 0; u < 5; u++) {
                acc.x += v[u].x; acc.y += v[u].y;
                acc.z += v[u].z; acc.w += v[u].w;
            }
        }
    } else {
        unsigned m = sel;
        while (m) {
            const int j = __ffs(m) - 1;
            m &= m - 1;
            const int nidx = __shfl_sync(FULL, my_neigh, j);
            const float4 v = F[(size_t)nidx * 32 + lane];
            acc.x += v.x; acc.y += v.y; acc.z += v.z; acc.w += v.w;
        }
    }

    const float inv = 1.0f / (float)ns;
    float4 o;
    o.x = fmaxf(acc.x * inv, 0.0f);
    o.y = fmaxf(acc.y * inv, 0.0f);
    o.z = fmaxf(acc.z * inv, 0.0f);
    o.w = fmaxf(acc.w * inv, 0.0f);
    __stcs(reinterpret_cast<float4*>(out) + (size_t)row * 32 + lane, o);
}

extern "C" void kernel_launch(void* const* d_in, const int* in_sizes, int n_in,
                              void* d_out, int out_size)
{
    const float* features = (const float*)d_in[0];
    const int*   nodes    = (const int*)d_in[1];
    const int*   neighs   = (const int*)d_in[2];
    const int*   nsamp    = (n_in >= 4) ? (const int*)d_in[3] : nullptr;
    float*       out      = (float*)d_out;

    const int B = in_sizes[1];

    const int blocks = (B + WARPS_PER_BLOCK - 1) / WARPS_PER_BLOCK;
    intra_agg_kernel<<<blocks, THREADS_PER_BLOCK>>>(features, nodes, neighs, nsamp,
                                                    out, B);
}

// round 8
// speedup vs baseline: 1.3422x; 1.0733x over previous
#include <cuda_runtime.h>
#include <cuda_bf16.h>

#define WARPS_PER_BLOCK 8
#define THREADS_PER_BLOCK (WARPS_PER_BLOCK * 32)

static __device__ __forceinline__ float merge_f(float a, float b, int w, int lane) {
    const unsigned FULL = 0xffffffffu;
    const float keep = (lane & w) ? b : a;
    const float send = (lane & w) ? a : b;
    return keep + __shfl_xor_sync(FULL, send, w);
}

// One warp per batch row. D=128 floats (row = 32 float4). K=32 (hardwired).
// Octet layout: 4 octets (8 lanes); slot s (0..7): octet o handles candidate
// c = 4s+o, its 512B row read as 4 x 128B chunks. Reductions deferred to
// group boundaries (2 groups x 4 slots) -> loop body is pure LDG+FMA.
__global__ __launch_bounds__(THREADS_PER_BLOCK, 4)
void intra_agg_kernel(const float* __restrict__ features,
                      const int*   __restrict__ nodes,
                      const int*   __restrict__ neighs,
                      const int*   __restrict__ nsamp,
                      float*       __restrict__ out,
                      int B)
{
    const unsigned FULL = 0xffffffffu;
    const int lane = threadIdx.x & 31;
    const int row  = blockIdx.x * WARPS_PER_BLOCK + (threadIdx.x >> 5);
    if (row >= B) return;

    const int ns = nsamp ? nsamp[0] : 10;

    const float4* __restrict__ F = reinterpret_cast<const float4*>(features);
    const int* __restrict__ nrow = neighs + (size_t)row * 32;

    const int my_neigh = nrow[lane];              // lane k owns candidate k
    const int oct      = lane >> 3;               // my octet (0..3)
    const int ol       = lane & 7;                // lane within octet

    // center row in octet-chunk layout: cc[t] = floats [4*(t*8+ol) ..)
    const float4* cbase = F + (size_t)nodes[row] * 32 + ol;
    float4 cc[4];
    #pragma unroll
    for (int t = 0; t < 4; t++) cc[t] = cbase[t * 8];

    // all 8 candidate indices for my octet, up front (independent shfls)
    int cidx[8];
    #pragma unroll
    for (int s = 0; s < 8; s++)
        cidx[s] = __shfl_sync(FULL, my_neigh, s * 4 + oct);

    // ---- Phase 1: 2 groups x 4 slots; body = pure LDG+FMA (free pipelining) ----
    float dred[2], nred[2];
    #pragma unroll
    for (int g = 0; g < 2; g++) {
        float dp[4], np[4];
        #pragma unroll
        for (int s4 = 0; s4 < 4; s4++) {
            const float4* base = F + (size_t)cidx[g * 4 + s4] * 32 + ol;
            float4 f[4];
            #pragma unroll
            for (int t = 0; t < 4; t++) f[t] = base[t * 8];

            float d = 0.0f, n = 0.0f;
            #pragma unroll
            for (int t = 0; t < 4; t++) {
                d = fmaf(cc[t].x, f[t].x, d);
                d = fmaf(cc[t].y, f[t].y, d);
                d = fmaf(cc[t].z, f[t].z, d);
                d = fmaf(cc[t].w, f[t].w, d);
                n = fmaf(f[t].x, f[t].x, n);
                n = fmaf(f[t].y, f[t].y, n);
                n = fmaf(f[t].z, f[t].z, n);
                n = fmaf(f[t].w, f[t].w, n);
            }
            dp[s4] = d; np[s4] = n;
        }

        // octet-local transpose-reduce of 4 values (lane ol ends holding
        // value vs = 2*bit2(ol) + bit1(ol))
        {
            float e0 = merge_f(dp[0], dp[2], 4, lane);
            float e1 = merge_f(dp[1], dp[3], 4, lane);
            float h  = merge_f(e0, e1, 2, lane);
            h += __shfl_xor_sync(FULL, h, 1);
            dred[g] = h;
        }
        {
            float e0 = merge_f(np[0], np[2], 4, lane);
            float e1 = merge_f(np[1], np[3], 4, lane);
            float h  = merge_f(e0, e1, 2, lane);
            h += __shfl_xor_sync(FULL, h, 1);
            nred[g] = h;
        }
    }

    // redistribute: candidate L = 4s+o is held (group s>>2, value s&3) at
    // lane 8*o + 4*((s&3)>>1) + 2*((s&3)&1)
    const int s  = lane >> 2;
    const int s4 = s & 3;
    const int src = ((lane & 3) << 3) + ((s4 >> 1) << 2) + ((s4 & 1) << 1);
    const float d0 = __shfl_sync(FULL, dred[0], src);
    const float d1 = __shfl_sync(FULL, dred[1], src);
    const float n0 = __shfl_sync(FULL, nred[0], src);
    const float n1 = __shfl_sync(FULL, nred[1], src);
    const float my_dot = (s < 4) ? d0 : d1;
    const float my_n2  = (s < 4) ? n0 : n1;

    // key = dot / ||neigh||  (center norm: common positive factor, dropped)
    float r = rsqrtf(my_n2);
    r = r * fmaf(-0.5f * my_n2, r * r, 1.5f);     // Newton -> ~fp32-exact
    const float my_key = my_dot * r;

    // ---- stable rank-by-counting (matches jax.lax.top_k tie-break) ----
    int rank = 0;
    #pragma unroll
    for (int j = 0; j < 32; j++) {
        const float kj = __shfl_sync(FULL, my_key, j);
        rank += (kj > my_key) || (kj == my_key && j < lane);
    }

    // ---- Phase 2: mean over selected neighbors ----
    const unsigned sel = __ballot_sync(FULL, rank < ns);
    float4 acc = make_float4(0.f, 0.f, 0.f, 0.f);

    if (ns == 10) {
        int src10[10];
        unsigned m = sel;
        #pragma unroll
        for (int i = 0; i < 10; i++) { src10[i] = __ffs(m) - 1; m &= m - 1; }
        int nid[10];
        #pragma unroll
        for (int i = 0; i < 10; i++) nid[i] = __shfl_sync(FULL, my_neigh, src10[i]);
        #pragma unroll
        for (int s0 = 0; s0 < 10; s0 += 5) {
            float4 v[5];
            #pragma unroll
            for (int u = 0; u < 5; u++)
                v[u] = F[(size_t)nid[s0 + u] * 32 + lane];
            #pragma unroll
            for (int u = 0; u < 5; u++) {
                acc.x += v[u].x; acc.y += v[u].y;
                acc.z += v[u].z; acc.w += v[u].w;
            }
        }
    } else {
        unsigned m = sel;
        while (m) {
            const int j = __ffs(m) - 1;
            m &= m - 1;
            const int nidx = __shfl_sync(FULL, my_neigh, j);
            const float4 v = F[(size_t)nidx * 32 + lane];
            acc.x += v.x; acc.y += v.y; acc.z += v.z; acc.w += v.w;
        }
    }

    const float inv = 1.0f / (float)ns;
    float4 o;
    o.x = fmaxf(acc.x * inv, 0.0f);
    o.y = fmaxf(acc.y * inv, 0.0f);
    o.z = fmaxf(acc.z * inv, 0.0f);
    o.w = fmaxf(acc.w * inv, 0.0f);
    __stcs(reinterpret_cast<float4*>(out) + (size_t)row * 32 + lane, o);
}

extern "C" void kernel_launch(void* const* d_in, const int* in_sizes, int n_in,
                              void* d_out, int out_size)
{
    const float* features = (const float*)d_in[0];
    const int*   nodes    = (const int*)d_in[1];
    const int*   neighs   = (const int*)d_in[2];
    const int*   nsamp    = (n_in >= 4) ? (const int*)d_in[3] : nullptr;
    float*       out      = (float*)d_out;

    const int B = in_sizes[1];

    const int blocks = (B + WARPS_PER_BLOCK - 1) / WARPS_PER_BLOCK;
    intra_agg_kernel<<<blocks, THREADS_PER_BLOCK>>>(features, nodes, neighs, nsamp,
                                                    out, B);
}